// round 9
// baseline (speedup 1.0000x reference)
#include <cuda_runtime.h>
#include <cstdint>

#define NT 256
#define B_TOTAL 262144
#define KPAD 448          // 386 padded to 14 * 32
#define NCHUNK 14

typedef unsigned long long u64;

// ---------------- scratch (static device globals: allowed) ----------------
__device__ float g_feats[(size_t)B_TOTAL * KPAD];   // [elem][448], tf32-rounded
__device__ float g_fc1p[128 * KPAD];                // [out][448], tf32-rounded, zero-padded

// ---------------- small helpers ----------------
__device__ __forceinline__ u64 pk2(float a, float b) {
    u64 r;
    asm("mov.b64 %0, {%1, %2};" : "=l"(r) : "r"(__float_as_uint(a)), "r"(__float_as_uint(b)));
    return r;
}
__device__ __forceinline__ void up2(u64 v, float& a, float& b) {
    unsigned lo, hi;
    asm("mov.b64 {%0, %1}, %2;" : "=r"(lo), "=r"(hi) : "l"(v));
    a = __uint_as_float(lo); b = __uint_as_float(hi);
}
__device__ __forceinline__ void fma2(u64& d, u64 a, u64 b) {
    asm("fma.rn.f32x2 %0, %1, %2, %0;" : "+l"(d) : "l"(a), "l"(b));
}
__device__ __forceinline__ float sg(float x) { return __fdividef(1.f, 1.f + __expf(-x)); }
__device__ __forceinline__ float th(float x) {   // tanh = 1 - 2/(1+e^{2x}), saturates correctly
    float e = __expf(2.f * x);
    return 1.f - __fdividef(2.f, 1.f + e);
}
__device__ __forceinline__ float tfr(float x) {   // round-to-nearest tf32
    unsigned u; asm("cvt.rna.tf32.f32 %0, %1;" : "=r"(u) : "f"(x));
    return __uint_as_float(u);
}
__device__ __forceinline__ void cpasync16(uint32_t dst, const void* src) {
    asm volatile("cp.async.cg.shared.global [%0], [%1], 16;" :: "r"(dst), "l"(src) : "memory");
}
__device__ __forceinline__ uint32_t smem_u32(const void* p) {
    uint32_t a;
    asm("{ .reg .u64 t; cvta.to.shared.u64 t, %1; cvt.u32.u64 %0, t; }" : "=r"(a) : "l"(p));
    return a;
}
__device__ __forceinline__ void mma_tf32(float4& c, uint32_t a0, uint32_t a1,
                                         uint32_t a2, uint32_t a3,
                                         uint32_t b0, uint32_t b1) {
    asm volatile(
        "mma.sync.aligned.m16n8k8.row.col.f32.tf32.tf32.f32 "
        "{%0,%1,%2,%3}, {%4,%5,%6,%7}, {%8,%9}, {%0,%1,%2,%3};"
        : "+f"(c.x), "+f"(c.y), "+f"(c.z), "+f"(c.w)
        : "r"(a0), "r"(a1), "r"(a2), "r"(a3), "r"(b0), "r"(b1));
}

// ==========================================================================
// Kernel A: 2-layer LSTM, TWO LANES per element (lane pair 2q, 2q+1).
// Lane p owns L1 units [4p,4p+4) and L2 units [8p,8p+8).
// Full h vectors rebuilt per step via shfl.xor(1).
// ==========================================================================
__global__ void __launch_bounds__(NT, 2)
lstm_kernel(const float* __restrict__ obs,
            const float* __restrict__ w_ih1, const float* __restrict__ w_hh1,
            const float* __restrict__ b_ih1, const float* __restrict__ b_hh1,
            const float* __restrict__ w_ih2, const float* __restrict__ w_hh2,
            const float* __restrict__ b_ih2, const float* __restrict__ b_hh2)
{
    __shared__ __align__(16) float smem[1984];
    float* s_w1 = smem;          // [11][8] float4 (i,f,g,o)  352
    float* s_b1 = smem + 352;    // [8] float4                 32
    float* s_w2 = smem + 384;    // [24][16] float4          1536
    float* s_b2 = smem + 1920;   // [16] float4                64

    const int tid = threadIdx.x;

    for (int idx = tid; idx < 88; idx += NT) {
        int k = idx >> 3, h = idx & 7;
        float4 v;
        if (k < 3) {
            v.x = w_ih1[h*3+k];      v.y = w_ih1[(8+h)*3+k];
            v.z = w_ih1[(16+h)*3+k]; v.w = w_ih1[(24+h)*3+k];
        } else {
            int kk = k - 3;
            v.x = w_hh1[h*8+kk];      v.y = w_hh1[(8+h)*8+kk];
            v.z = w_hh1[(16+h)*8+kk]; v.w = w_hh1[(24+h)*8+kk];
        }
        ((float4*)s_w1)[idx] = v;
    }
    if (tid < 8) {
        float4 v;
        v.x = b_ih1[tid]    + b_hh1[tid];
        v.y = b_ih1[8+tid]  + b_hh1[8+tid];
        v.z = b_ih1[16+tid] + b_hh1[16+tid];
        v.w = b_ih1[24+tid] + b_hh1[24+tid];
        ((float4*)s_b1)[tid] = v;
    }
    for (int idx = tid; idx < 384; idx += NT) {
        int k = idx >> 4, h = idx & 15;
        float4 v;
        if (k < 8) {
            v.x = w_ih2[h*8+k];      v.y = w_ih2[(16+h)*8+k];
            v.z = w_ih2[(32+h)*8+k]; v.w = w_ih2[(48+h)*8+k];
        } else {
            int kk = k - 8;
            v.x = w_hh2[h*16+kk];      v.y = w_hh2[(16+h)*16+kk];
            v.z = w_hh2[(32+h)*16+kk]; v.w = w_hh2[(48+h)*16+kk];
        }
        ((float4*)s_w2)[idx] = v;
    }
    if (tid < 16) {
        float4 v;
        v.x = b_ih2[tid]    + b_hh2[tid];
        v.y = b_ih2[16+tid] + b_hh2[16+tid];
        v.z = b_ih2[32+tid] + b_hh2[32+tid];
        v.w = b_ih2[48+tid] + b_hh2[48+tid];
        ((float4*)s_b2)[tid] = v;
    }
    __syncthreads();

    const ulonglong2* w1v = (const ulonglong2*)s_w1;
    const ulonglong2* b1v = (const ulonglong2*)s_b1;
    const ulonglong2* w2v = (const ulonglong2*)s_w2;
    const ulonglong2* b2v = (const ulonglong2*)s_b2;

    const int gthread = blockIdx.x * NT + tid;
    const int e = gthread >> 1;            // element index
    const int p = tid & 1;                 // lane-in-pair
    const float* orow = obs + (size_t)e * 74;
    float* frow = g_feats + (size_t)e * KPAD;
    const unsigned FULL = 0xFFFFFFFFu;

    // own state: L1 units p*4+j, L2 units p*8+j
    float h1o[4], c1o[4], h2o[8], c2o[8];
    #pragma unroll
    for (int j = 0; j < 4; j++) { h1o[j] = 0.f; c1o[j] = 0.f; }
    #pragma unroll
    for (int j = 0; j < 8; j++) { h2o[j] = 0.f; c2o[j] = 0.f; }

    #pragma unroll 1
    for (int t = 0; t < 24; t++) {
        float xv[3];
        xv[0] = __ldg(orow + t);
        xv[1] = __ldg(orow + 24 + t);
        xv[2] = __ldg(orow + 48 + t);

        // ---- gather full h1(prev), h2(prev) via pair shuffle ----
        float h1f[8], h2f[16];
        #pragma unroll
        for (int j = 0; j < 4; j++) {
            float sh = __shfl_xor_sync(FULL, h1o[j], 1);
            h1f[j]     = p ? sh : h1o[j];
            h1f[4 + j] = p ? h1o[j] : sh;
        }
        #pragma unroll
        for (int j = 0; j < 8; j++) {
            float sh = __shfl_xor_sync(FULL, h2o[j], 1);
            h2f[j]     = p ? sh : h2o[j];
            h2f[8 + j] = p ? h2o[j] : sh;
        }

        // ---- LSTM layer 1: own 4 units ----
        u64 aif[4], ago[4];
        #pragma unroll
        for (int j = 0; j < 4; j++) {
            ulonglong2 b = b1v[p*4 + j];
            aif[j] = b.x; ago[j] = b.y;
        }
        #pragma unroll
        for (int k = 0; k < 11; k++) {
            float m = (k < 3) ? xv[k] : h1f[k-3];
            u64 mk = pk2(m, m);
            #pragma unroll
            for (int j = 0; j < 4; j++) {
                ulonglong2 w = w1v[k*8 + p*4 + j];
                fma2(aif[j], w.x, mk);
                fma2(ago[j], w.y, mk);
            }
        }
        #pragma unroll
        for (int j = 0; j < 4; j++) {
            float gi, gf, gg, go;
            up2(aif[j], gi, gf); up2(ago[j], gg, go);
            float c = sg(gf) * c1o[j] + sg(gi) * th(gg);
            c1o[j] = c;
            h1o[j] = sg(go) * th(c);
        }

        // ---- gather full h1(new) ----
        float h1nf[8];
        #pragma unroll
        for (int j = 0; j < 4; j++) {
            float sh = __shfl_xor_sync(FULL, h1o[j], 1);
            h1nf[j]     = p ? sh : h1o[j];
            h1nf[4 + j] = p ? h1o[j] : sh;
        }

        // ---- LSTM layer 2: own 8 units, single pass ----
        u64 a2[8], g2[8];
        #pragma unroll
        for (int j = 0; j < 8; j++) {
            ulonglong2 b = b2v[p*8 + j];
            a2[j] = b.x; g2[j] = b.y;
        }
        #pragma unroll
        for (int k = 0; k < 24; k++) {
            float m = (k < 8) ? h1nf[k] : h2f[k-8];
            u64 mk = pk2(m, m);
            #pragma unroll
            for (int j = 0; j < 8; j++) {
                ulonglong2 w = w2v[k*16 + p*8 + j];
                fma2(a2[j], w.x, mk);
                fma2(g2[j], w.y, mk);
            }
        }
        #pragma unroll
        for (int j = 0; j < 8; j++) {
            float gi, gf, gg, go;
            up2(a2[j], gi, gf); up2(g2[j], gg, go);
            float c = sg(gf) * c2o[j] + sg(gi) * th(gg);
            c2o[j] = c;
            h2o[j] = sg(go) * th(c);
        }

        // ---- store own h2 (tf32-rounded) into feats ----
        float* fr = frow + t * 16 + p * 8;
        #pragma unroll
        for (int q = 0; q < 2; q++) {
            float4 v;
            v.x = tfr(h2o[4*q+0]); v.y = tfr(h2o[4*q+1]);
            v.z = tfr(h2o[4*q+2]); v.w = tfr(h2o[4*q+3]);
            ((float4*)fr)[q] = v;
        }
    }

    // ---- tail: u features + zero padding (cols 384..447), split across pair ----
    float4 z; z.x = z.y = z.z = z.w = 0.f;
    if (p == 0) {
        float4 v; v.x = tfr(__ldg(orow + 72)); v.y = tfr(__ldg(orow + 73)); v.z = 0.f; v.w = 0.f;
        ((float4*)(frow + 384))[0] = v;
        #pragma unroll
        for (int q = 0; q < 7; q++) ((float4*)(frow + 388))[q] = z;   // 388..415
    } else {
        #pragma unroll
        for (int q = 0; q < 8; q++) ((float4*)(frow + 416))[q] = z;   // 416..447
    }
}

// ==========================================================================
// Kernel P: pad + tf32-round fc1 weights
// ==========================================================================
__global__ void pad_kernel(const float* __restrict__ fc1_w)
{
    int idx = blockIdx.x * blockDim.x + threadIdx.x;
    if (idx >= 128 * KPAD) return;
    int j = idx / KPAD, k = idx - j * KPAD;
    g_fc1p[idx] = (k < 386) ? tfr(fc1_w[j * 386 + k]) : 0.f;
}

// ==========================================================================
// Kernel B: tf32 mma.sync GEMM (M-tile 128, N=128, K=448) + FC2 epilogue
// 2 CTAs/SM: dyn smem 73728B, 8 warps x 16 rows each.
// ==========================================================================
// dynamic smem (floats):
//   A bufs: 2 x (128 rows x 36) = 9216
//   B bufs: 2 x (128 rows x 36) = 9216   (offset 9216)
//   C scratch (reused region):  128 x 133 = 17024  -> dyn = 18432 floats
#define A_STRIDE 36
#define C_STRIDE 133
#define FCDYN_FLOATS 18432

__global__ void __launch_bounds__(256, 2)
fc_kernel(const float* __restrict__ fc1_b,
          const float* __restrict__ fc2_w, const float* __restrict__ fc2_b,
          float* __restrict__ out)
{
    extern __shared__ float smf[];
    __shared__ __align__(16) float s_fc2[3072];    // [k][a] transposed
    __shared__ __align__(16) float s_fc1b[128];
    __shared__ __align__(16) float s_fc2b[24];

    const int tid  = threadIdx.x;
    const int wid  = tid >> 5;
    const int lane = tid & 31;
    const int laneRow = lane >> 2;     // 0..7
    const int laneCol = lane & 3;      // 0..3
    const int wbase = wid * 16;        // warp's 16-row slice of the 128-row tile

    const uint32_t sbase = smem_u32(smf);
    const uint32_t aBuf[2] = { sbase,              sbase + 4608u * 4u };
    const uint32_t bBuf[2] = { sbase + 9216u * 4u, sbase + 13824u * 4u };

    // stage FC2 weights + biases
    for (int idx = tid; idx < 3072; idx += 256) {
        int a = idx >> 7, k = idx & 127;
        s_fc2[k * 24 + a] = fc2_w[idx];
    }
    if (tid < 128) s_fc1b[tid] = fc1_b[tid];
    if (tid < 24)  s_fc2b[tid] = fc2_b[tid];

    const int m0 = blockIdx.x * 128;
    const int row  = tid >> 1;          // 0..127 (A and B copy rows)
    const int half = (tid & 1) * 16;
    const float* arow = g_feats + (size_t)(m0 + row) * KPAD + half;
    const float* brow = g_fc1p + (size_t)row * KPAD + half;
    const uint32_t smDstOff = ((uint32_t)row * A_STRIDE + half) * 4u;

    // ---- prefetch chunk 0 ----
    {
        #pragma unroll
        for (int c = 0; c < 4; c++) cpasync16(aBuf[0] + smDstOff + c * 16, arow + c * 4);
        #pragma unroll
        for (int c = 0; c < 4; c++) cpasync16(bBuf[0] + smDstOff + c * 16, brow + c * 4);
        asm volatile("cp.async.commit_group;" ::: "memory");
    }

    float4 acc[16];
    #pragma unroll
    for (int nt = 0; nt < 16; nt++) acc[nt] = make_float4(0.f, 0.f, 0.f, 0.f);

    #pragma unroll 1
    for (int ch = 0; ch < NCHUNK; ch++) {
        if (ch + 1 < NCHUNK) {
            const int nb = (ch + 1) & 1;
            const float* as = arow + (ch + 1) * 32;
            const float* bs = brow + (ch + 1) * 32;
            #pragma unroll
            for (int c = 0; c < 4; c++) cpasync16(aBuf[nb] + smDstOff + c * 16, as + c * 4);
            #pragma unroll
            for (int c = 0; c < 4; c++) cpasync16(bBuf[nb] + smDstOff + c * 16, bs + c * 4);
            asm volatile("cp.async.commit_group;" ::: "memory");
            asm volatile("cp.async.wait_group 1;" ::: "memory");
        } else {
            asm volatile("cp.async.wait_group 0;" ::: "memory");
        }
        __syncthreads();

        const int buf = ch & 1;
        const float* A  = smf + buf * 4608;
        const float* Bp = smf + 9216 + buf * 4608;

        #pragma unroll
        for (int kk = 0; kk < 4; kk++) {
            const int kc = kk * 8 + laneCol;
            uint32_t b0[16], b1[16];
            #pragma unroll
            for (int nt = 0; nt < 16; nt++) {
                const float* bp = Bp + (nt * 8 + laneRow) * A_STRIDE + kc;
                b0[nt] = __float_as_uint(bp[0]);
                b1[nt] = __float_as_uint(bp[4]);
            }
            const float* ap = A + (wbase + laneRow) * A_STRIDE + kc;
            uint32_t a0 = __float_as_uint(ap[0]);
            uint32_t a1 = __float_as_uint(ap[8 * A_STRIDE]);
            uint32_t a2 = __float_as_uint(ap[4]);
            uint32_t a3 = __float_as_uint(ap[8 * A_STRIDE + 4]);
            #pragma unroll
            for (int nt = 0; nt < 16; nt++)
                mma_tf32(acc[nt], a0, a1, a2, a3, b0[nt], b1[nt]);
        }
        __syncthreads();
    }

    // ---- write C into smem (row-major, stride 133; scalar stores = aligned) ----
    {
        const int rbase = wbase + laneRow;
        #pragma unroll
        for (int nt = 0; nt < 16; nt++) {
            const int col = nt * 8 + 2 * laneCol;
            smf[(size_t)rbase * C_STRIDE + col]           = acc[nt].x;
            smf[(size_t)rbase * C_STRIDE + col + 1]       = acc[nt].y;
            smf[(size_t)(rbase + 8) * C_STRIDE + col]     = acc[nt].z;
            smf[(size_t)(rbase + 8) * C_STRIDE + col + 1] = acc[nt].w;
        }
    }
    __syncthreads();

    // threads 0..127 each handle output row m0 + tid
    if (tid < 128) {
        const float* crow = smf + (size_t)tid * C_STRIDE;
        u64 y[12];
        {
            const ulonglong2* bb = (const ulonglong2*)s_fc2b;
            #pragma unroll
            for (int q = 0; q < 6; q++) { ulonglong2 b = bb[q]; y[2*q] = b.x; y[2*q+1] = b.y; }
        }
        const ulonglong2* fc2v = (const ulonglong2*)s_fc2;
        #pragma unroll 4
        for (int j = 0; j < 128; j++) {
            float v = crow[j] + s_fc1b[j];
            v = fmaxf(v, 0.f);
            u64 vk = pk2(v, v);
            const ulonglong2* wr = fc2v + j * 6;
            #pragma unroll
            for (int q = 0; q < 6; q++) {
                ulonglong2 w = wr[q];
                fma2(y[2*q],   w.x, vk);
                fma2(y[2*q+1], w.y, vk);
            }
        }
        float* op = out + (size_t)(m0 + tid) * 24;
        #pragma unroll
        for (int q = 0; q < 6; q++) {
            float a0, a1, a2, a3;
            up2(y[2*q], a0, a1); up2(y[2*q+1], a2, a3);
            float4 o;
            o.x = __fdividef(a0, 1.f + fabsf(a0));
            o.y = __fdividef(a1, 1.f + fabsf(a1));
            o.z = __fdividef(a2, 1.f + fabsf(a2));
            o.w = __fdividef(a3, 1.f + fabsf(a3));
            ((float4*)op)[q] = o;
        }
    }
}

// ==========================================================================
extern "C" void kernel_launch(void* const* d_in, const int* in_sizes, int n_in,
                              void* d_out, int out_size)
{
    const float* obs   = (const float*)d_in[0];
    const float* w_ih1 = (const float*)d_in[1];
    const float* w_hh1 = (const float*)d_in[2];
    const float* b_ih1 = (const float*)d_in[3];
    const float* b_hh1 = (const float*)d_in[4];
    const float* w_ih2 = (const float*)d_in[5];
    const float* w_hh2 = (const float*)d_in[6];
    const float* b_ih2 = (const float*)d_in[7];
    const float* b_hh2 = (const float*)d_in[8];
    const float* fc1_w = (const float*)d_in[9];
    const float* fc1_b = (const float*)d_in[10];
    const float* fc2_w = (const float*)d_in[11];
    const float* fc2_b = (const float*)d_in[12];
    float* out = (float*)d_out;

    // 2 lanes per element: 524288 threads
    lstm_kernel<<<(2 * B_TOTAL) / NT, NT>>>(obs, w_ih1, w_hh1, b_ih1, b_hh1,
                                            w_ih2, w_hh2, b_ih2, b_hh2);

    pad_kernel<<<(128 * KPAD + 1023) / 1024, 1024>>>(fc1_w);

    const size_t dyn = FCDYN_FLOATS * sizeof(float);   // 73728 B
    cudaFuncSetAttribute(fc_kernel, cudaFuncAttributeMaxDynamicSharedMemorySize, (int)dyn);
    fc_kernel<<<B_TOTAL / 128, 256, dyn>>>(fc1_b, fc2_w, fc2_b, out);
}

// round 11
// speedup vs baseline: 1.1175x; 1.1175x over previous
#include <cuda_runtime.h>
#include <cstdint>

#define NTL 128           // lstm kernel block size
#define NT 256
#define B_TOTAL 262144
#define KPAD 448          // 386 padded to 14 * 32
#define NCHUNK 14

typedef unsigned long long u64;

// ---------------- scratch (static device globals: allowed) ----------------
__device__ float g_feats[(size_t)B_TOTAL * KPAD];   // [elem][448], tf32-rounded
__device__ float g_fc1p[128 * KPAD];                // [out][448], tf32-rounded, zero-padded

// ---------------- small helpers ----------------
__device__ __forceinline__ u64 pk2(float a, float b) {
    u64 r;
    asm("mov.b64 %0, {%1, %2};" : "=l"(r) : "r"(__float_as_uint(a)), "r"(__float_as_uint(b)));
    return r;
}
__device__ __forceinline__ void up2(u64 v, float& a, float& b) {
    unsigned lo, hi;
    asm("mov.b64 {%0, %1}, %2;" : "=r"(lo), "=r"(hi) : "l"(v));
    a = __uint_as_float(lo); b = __uint_as_float(hi);
}
__device__ __forceinline__ void fma2(u64& d, u64 a, u64 b) {
    asm("fma.rn.f32x2 %0, %1, %2, %0;" : "+l"(d) : "l"(a), "l"(b));
}
__device__ __forceinline__ float sg(float x) { return __fdividef(1.f, 1.f + __expf(-x)); }
__device__ __forceinline__ float th(float x) {   // tanh = 1 - 2/(1+e^{2x}), saturates correctly
    float e = __expf(2.f * x);
    return 1.f - __fdividef(2.f, 1.f + e);
}
__device__ __forceinline__ float tfr(float x) {   // round-to-nearest tf32
    unsigned u; asm("cvt.rna.tf32.f32 %0, %1;" : "=r"(u) : "f"(x));
    return __uint_as_float(u);
}
__device__ __forceinline__ void cpasync16(uint32_t dst, const void* src) {
    asm volatile("cp.async.cg.shared.global [%0], [%1], 16;" :: "r"(dst), "l"(src) : "memory");
}
__device__ __forceinline__ uint32_t smem_u32(const void* p) {
    uint32_t a;
    asm("{ .reg .u64 t; cvta.to.shared.u64 t, %1; cvt.u32.u64 %0, t; }" : "=r"(a) : "l"(p));
    return a;
}
__device__ __forceinline__ void mma_tf32(float4& c, uint32_t a0, uint32_t a1,
                                         uint32_t a2, uint32_t a3,
                                         uint32_t b0, uint32_t b1) {
    asm volatile(
        "mma.sync.aligned.m16n8k8.row.col.f32.tf32.tf32.f32 "
        "{%0,%1,%2,%3}, {%4,%5,%6,%7}, {%8,%9}, {%0,%1,%2,%3};"
        : "+f"(c.x), "+f"(c.y), "+f"(c.z), "+f"(c.w)
        : "r"(a0), "r"(a1), "r"(a2), "r"(a3), "r"(b0), "r"(b1));
}

// ==========================================================================
// Kernel A: 2-layer LSTM, 2 elements per thread (weight LDS amortized x2),
// gate computation blocked in 4-unit passes to cap registers; occupancy 3.
// ==========================================================================
__global__ void __launch_bounds__(NTL, 3)
lstm_kernel(const float* __restrict__ obs,
            const float* __restrict__ w_ih1, const float* __restrict__ w_hh1,
            const float* __restrict__ b_ih1, const float* __restrict__ b_hh1,
            const float* __restrict__ w_ih2, const float* __restrict__ w_hh2,
            const float* __restrict__ b_ih2, const float* __restrict__ b_hh2)
{
    __shared__ __align__(16) float smem[1984];
    float* s_w1 = smem;          // [11][8] float4 (i,f,g,o)  352
    float* s_b1 = smem + 352;    // [8] float4                 32
    float* s_w2 = smem + 384;    // [24][16] float4          1536
    float* s_b2 = smem + 1920;   // [16] float4                64

    const int tid = threadIdx.x;

    for (int idx = tid; idx < 88; idx += NTL) {
        int k = idx >> 3, h = idx & 7;
        float4 v;
        if (k < 3) {
            v.x = w_ih1[h*3+k];      v.y = w_ih1[(8+h)*3+k];
            v.z = w_ih1[(16+h)*3+k]; v.w = w_ih1[(24+h)*3+k];
        } else {
            int kk = k - 3;
            v.x = w_hh1[h*8+kk];      v.y = w_hh1[(8+h)*8+kk];
            v.z = w_hh1[(16+h)*8+kk]; v.w = w_hh1[(24+h)*8+kk];
        }
        ((float4*)s_w1)[idx] = v;
    }
    if (tid < 8) {
        float4 v;
        v.x = b_ih1[tid]    + b_hh1[tid];
        v.y = b_ih1[8+tid]  + b_hh1[8+tid];
        v.z = b_ih1[16+tid] + b_hh1[16+tid];
        v.w = b_ih1[24+tid] + b_hh1[24+tid];
        ((float4*)s_b1)[tid] = v;
    }
    for (int idx = tid; idx < 384; idx += NTL) {
        int k = idx >> 4, h = idx & 15;
        float4 v;
        if (k < 8) {
            v.x = w_ih2[h*8+k];      v.y = w_ih2[(16+h)*8+k];
            v.z = w_ih2[(32+h)*8+k]; v.w = w_ih2[(48+h)*8+k];
        } else {
            int kk = k - 8;
            v.x = w_hh2[h*16+kk];      v.y = w_hh2[(16+h)*16+kk];
            v.z = w_hh2[(32+h)*16+kk]; v.w = w_hh2[(48+h)*16+kk];
        }
        ((float4*)s_w2)[idx] = v;
    }
    if (tid < 16) {
        float4 v;
        v.x = b_ih2[tid]    + b_hh2[tid];
        v.y = b_ih2[16+tid] + b_hh2[16+tid];
        v.z = b_ih2[32+tid] + b_hh2[32+tid];
        v.w = b_ih2[48+tid] + b_hh2[48+tid];
        ((float4*)s_b2)[tid] = v;
    }
    __syncthreads();

    const ulonglong2* w1v = (const ulonglong2*)s_w1;
    const ulonglong2* b1v = (const ulonglong2*)s_b1;
    const ulonglong2* w2v = (const ulonglong2*)s_w2;
    const ulonglong2* b2v = (const ulonglong2*)s_b2;

    const int e0 = blockIdx.x * (2 * NTL) + tid;
    const int e1 = e0 + NTL;
    const float* o0 = obs + (size_t)e0 * 74;
    const float* o1 = obs + (size_t)e1 * 74;
    float* f0 = g_feats + (size_t)e0 * KPAD;
    float* f1 = g_feats + (size_t)e1 * KPAD;

    float h1[2][8], c1[2][8], h2[2][16], c2[2][16];
    #pragma unroll
    for (int h = 0; h < 8; h++)  { h1[0][h]=h1[1][h]=0.f; c1[0][h]=c1[1][h]=0.f; }
    #pragma unroll
    for (int h = 0; h < 16; h++) { h2[0][h]=h2[1][h]=0.f; c2[0][h]=c2[1][h]=0.f; }

    #pragma unroll 1
    for (int t = 0; t < 24; t++) {
        float x0[3], x1[3];
        x0[0] = __ldg(o0 + t); x0[1] = __ldg(o0 + 24 + t); x0[2] = __ldg(o0 + 48 + t);
        x1[0] = __ldg(o1 + t); x1[1] = __ldg(o1 + 24 + t); x1[2] = __ldg(o1 + 48 + t);

        // ---- LSTM layer 1: two 4-unit passes (accs capped at 16 u64) ----
        float h1n[2][8];
        #pragma unroll
        for (int q = 0; q < 2; q++) {
            const int u0 = q * 4;
            u64 aif[2][4], ago[2][4];
            #pragma unroll
            for (int j = 0; j < 4; j++) {
                ulonglong2 b = b1v[u0 + j];
                aif[0][j] = b.x; ago[0][j] = b.y;
                aif[1][j] = b.x; ago[1][j] = b.y;
            }
            #pragma unroll
            for (int k = 0; k < 11; k++) {
                float m0 = (k < 3) ? x0[k] : h1[0][k-3];
                float m1 = (k < 3) ? x1[k] : h1[1][k-3];
                u64 mk0 = pk2(m0, m0), mk1 = pk2(m1, m1);
                #pragma unroll
                for (int j = 0; j < 4; j++) {
                    ulonglong2 w = w1v[k*8 + u0 + j];
                    fma2(aif[0][j], w.x, mk0); fma2(ago[0][j], w.y, mk0);
                    fma2(aif[1][j], w.x, mk1); fma2(ago[1][j], w.y, mk1);
                }
            }
            #pragma unroll
            for (int e = 0; e < 2; e++)
                #pragma unroll
                for (int j = 0; j < 4; j++) {
                    float gi, gf, gg, go;
                    up2(aif[e][j], gi, gf); up2(ago[e][j], gg, go);
                    float c = sg(gf) * c1[e][u0+j] + sg(gi) * th(gg);
                    c1[e][u0+j] = c;
                    h1n[e][u0+j] = sg(go) * th(c);
                }
        }

        // ---- LSTM layer 2: four 4-unit passes ----
        float h2n[2][16];
        #pragma unroll
        for (int q = 0; q < 4; q++) {
            const int u0 = q * 4;
            u64 a2[2][4], g2[2][4];
            #pragma unroll
            for (int j = 0; j < 4; j++) {
                ulonglong2 b = b2v[u0 + j];
                a2[0][j] = b.x; g2[0][j] = b.y;
                a2[1][j] = b.x; g2[1][j] = b.y;
            }
            #pragma unroll
            for (int k = 0; k < 24; k++) {
                float m0 = (k < 8) ? h1n[0][k] : h2[0][k-8];
                float m1 = (k < 8) ? h1n[1][k] : h2[1][k-8];
                u64 mk0 = pk2(m0, m0), mk1 = pk2(m1, m1);
                #pragma unroll
                for (int j = 0; j < 4; j++) {
                    ulonglong2 w = w2v[k*16 + u0 + j];
                    fma2(a2[0][j], w.x, mk0); fma2(g2[0][j], w.y, mk0);
                    fma2(a2[1][j], w.x, mk1); fma2(g2[1][j], w.y, mk1);
                }
            }
            #pragma unroll
            for (int e = 0; e < 2; e++) {
                #pragma unroll
                for (int j = 0; j < 4; j++) {
                    float gi, gf, gg, go;
                    up2(a2[e][j], gi, gf); up2(g2[e][j], gg, go);
                    float c = sg(gf) * c2[e][u0+j] + sg(gi) * th(gg);
                    c2[e][u0+j] = c;
                    h2n[e][u0+j] = sg(go) * th(c);
                }
                // stream this 4-unit chunk to feats (16B-aligned float4)
                float4 v;
                v.x = tfr(h2n[e][u0+0]); v.y = tfr(h2n[e][u0+1]);
                v.z = tfr(h2n[e][u0+2]); v.w = tfr(h2n[e][u0+3]);
                float* fe = (e == 0) ? f0 : f1;
                *(float4*)(fe + t * 16 + u0) = v;
            }
        }

        // ---- advance recurrent state ----
        #pragma unroll
        for (int h = 0; h < 8; h++)  { h1[0][h] = h1n[0][h]; h1[1][h] = h1n[1][h]; }
        #pragma unroll
        for (int h = 0; h < 16; h++) { h2[0][h] = h2n[0][h]; h2[1][h] = h2n[1][h]; }
    }

    // ---- tail: u features + zero padding (cols 384..447) ----
    #pragma unroll
    for (int e = 0; e < 2; e++) {
        const float* oe = (e == 0) ? o0 : o1;
        float* fe = (e == 0) ? f0 : f1;
        float4 v; v.x = tfr(__ldg(oe + 72)); v.y = tfr(__ldg(oe + 73)); v.z = 0.f; v.w = 0.f;
        ((float4*)(fe + 384))[0] = v;
        float4 z; z.x = z.y = z.z = z.w = 0.f;
        #pragma unroll
        for (int q = 0; q < 15; q++) ((float4*)(fe + 388))[q] = z;
    }
}

// ==========================================================================
// Kernel P: pad + tf32-round fc1 weights
// ==========================================================================
__global__ void pad_kernel(const float* __restrict__ fc1_w)
{
    int idx = blockIdx.x * blockDim.x + threadIdx.x;
    if (idx >= 128 * KPAD) return;
    int j = idx / KPAD, k = idx - j * KPAD;
    g_fc1p[idx] = (k < 386) ? tfr(fc1_w[j * 386 + k]) : 0.f;
}

// ==========================================================================
// Kernel B: tf32 mma.sync GEMM (M-tile 128, N=128, K=448) + FC2 epilogue
// 2 CTAs/SM: dyn smem 73728B, 8 warps x 16 rows each.
// ==========================================================================
#define A_STRIDE 36
#define C_STRIDE 133
#define FCDYN_FLOATS 18432

__global__ void __launch_bounds__(256, 2)
fc_kernel(const float* __restrict__ fc1_b,
          const float* __restrict__ fc2_w, const float* __restrict__ fc2_b,
          float* __restrict__ out)
{
    extern __shared__ float smf[];
    __shared__ __align__(16) float s_fc2[3072];    // [k][a] transposed
    __shared__ __align__(16) float s_fc1b[128];
    __shared__ __align__(16) float s_fc2b[24];

    const int tid  = threadIdx.x;
    const int wid  = tid >> 5;
    const int lane = tid & 31;
    const int laneRow = lane >> 2;     // 0..7
    const int laneCol = lane & 3;      // 0..3
    const int wbase = wid * 16;        // warp's 16-row slice of the 128-row tile

    const uint32_t sbase = smem_u32(smf);
    const uint32_t aBuf[2] = { sbase,              sbase + 4608u * 4u };
    const uint32_t bBuf[2] = { sbase + 9216u * 4u, sbase + 13824u * 4u };

    // stage FC2 weights + biases
    for (int idx = tid; idx < 3072; idx += 256) {
        int a = idx >> 7, k = idx & 127;
        s_fc2[k * 24 + a] = fc2_w[idx];
    }
    if (tid < 128) s_fc1b[tid] = fc1_b[tid];
    if (tid < 24)  s_fc2b[tid] = fc2_b[tid];

    const int m0 = blockIdx.x * 128;
    const int row  = tid >> 1;          // 0..127 (A and B copy rows)
    const int half = (tid & 1) * 16;
    const float* arow = g_feats + (size_t)(m0 + row) * KPAD + half;
    const float* brow = g_fc1p + (size_t)row * KPAD + half;
    const uint32_t smDstOff = ((uint32_t)row * A_STRIDE + half) * 4u;

    // ---- prefetch chunk 0 ----
    {
        #pragma unroll
        for (int c = 0; c < 4; c++) cpasync16(aBuf[0] + smDstOff + c * 16, arow + c * 4);
        #pragma unroll
        for (int c = 0; c < 4; c++) cpasync16(bBuf[0] + smDstOff + c * 16, brow + c * 4);
        asm volatile("cp.async.commit_group;" ::: "memory");
    }

    float4 acc[16];
    #pragma unroll
    for (int nt = 0; nt < 16; nt++) acc[nt] = make_float4(0.f, 0.f, 0.f, 0.f);

    #pragma unroll 1
    for (int ch = 0; ch < NCHUNK; ch++) {
        if (ch + 1 < NCHUNK) {
            const int nb = (ch + 1) & 1;
            const float* as = arow + (ch + 1) * 32;
            const float* bs = brow + (ch + 1) * 32;
            #pragma unroll
            for (int c = 0; c < 4; c++) cpasync16(aBuf[nb] + smDstOff + c * 16, as + c * 4);
            #pragma unroll
            for (int c = 0; c < 4; c++) cpasync16(bBuf[nb] + smDstOff + c * 16, bs + c * 4);
            asm volatile("cp.async.commit_group;" ::: "memory");
            asm volatile("cp.async.wait_group 1;" ::: "memory");
        } else {
            asm volatile("cp.async.wait_group 0;" ::: "memory");
        }
        __syncthreads();

        const int buf = ch & 1;
        const float* A  = smf + buf * 4608;
        const float* Bp = smf + 9216 + buf * 4608;

        #pragma unroll
        for (int kk = 0; kk < 4; kk++) {
            const int kc = kk * 8 + laneCol;
            uint32_t b0[16], b1[16];
            #pragma unroll
            for (int nt = 0; nt < 16; nt++) {
                const float* bp = Bp + (nt * 8 + laneRow) * A_STRIDE + kc;
                b0[nt] = __float_as_uint(bp[0]);
                b1[nt] = __float_as_uint(bp[4]);
            }
            const float* ap = A + (wbase + laneRow) * A_STRIDE + kc;
            uint32_t a0 = __float_as_uint(ap[0]);
            uint32_t a1 = __float_as_uint(ap[8 * A_STRIDE]);
            uint32_t a2 = __float_as_uint(ap[4]);
            uint32_t a3 = __float_as_uint(ap[8 * A_STRIDE + 4]);
            #pragma unroll
            for (int nt = 0; nt < 16; nt++)
                mma_tf32(acc[nt], a0, a1, a2, a3, b0[nt], b1[nt]);
        }
        __syncthreads();
    }

    // ---- write C into smem (row-major, stride 133; scalar stores = aligned) ----
    {
        const int rbase = wbase + laneRow;
        #pragma unroll
        for (int nt = 0; nt < 16; nt++) {
            const int col = nt * 8 + 2 * laneCol;
            smf[(size_t)rbase * C_STRIDE + col]           = acc[nt].x;
            smf[(size_t)rbase * C_STRIDE + col + 1]       = acc[nt].y;
            smf[(size_t)(rbase + 8) * C_STRIDE + col]     = acc[nt].z;
            smf[(size_t)(rbase + 8) * C_STRIDE + col + 1] = acc[nt].w;
        }
    }
    __syncthreads();

    // threads 0..127 each handle output row m0 + tid
    if (tid < 128) {
        const float* crow = smf + (size_t)tid * C_STRIDE;
        u64 y[12];
        {
            const ulonglong2* bb = (const ulonglong2*)s_fc2b;
            #pragma unroll
            for (int q = 0; q < 6; q++) { ulonglong2 b = bb[q]; y[2*q] = b.x; y[2*q+1] = b.y; }
        }
        const ulonglong2* fc2v = (const ulonglong2*)s_fc2;
        #pragma unroll 4
        for (int j = 0; j < 128; j++) {
            float v = crow[j] + s_fc1b[j];
            v = fmaxf(v, 0.f);
            u64 vk = pk2(v, v);
            const ulonglong2* wr = fc2v + j * 6;
            #pragma unroll
            for (int q = 0; q < 6; q++) {
                ulonglong2 w = wr[q];
                fma2(y[2*q],   w.x, vk);
                fma2(y[2*q+1], w.y, vk);
            }
        }
        float* op = out + (size_t)(m0 + tid) * 24;
        #pragma unroll
        for (int q = 0; q < 6; q++) {
            float a0, a1, a2, a3;
            up2(y[2*q], a0, a1); up2(y[2*q+1], a2, a3);
            float4 o;
            o.x = __fdividef(a0, 1.f + fabsf(a0));
            o.y = __fdividef(a1, 1.f + fabsf(a1));
            o.z = __fdividef(a2, 1.f + fabsf(a2));
            o.w = __fdividef(a3, 1.f + fabsf(a3));
            ((float4*)op)[q] = o;
        }
    }
}

// ==========================================================================
extern "C" void kernel_launch(void* const* d_in, const int* in_sizes, int n_in,
                              void* d_out, int out_size)
{
    const float* obs   = (const float*)d_in[0];
    const float* w_ih1 = (const float*)d_in[1];
    const float* w_hh1 = (const float*)d_in[2];
    const float* b_ih1 = (const float*)d_in[3];
    const float* b_hh1 = (const float*)d_in[4];
    const float* w_ih2 = (const float*)d_in[5];
    const float* w_hh2 = (const float*)d_in[6];
    const float* b_ih2 = (const float*)d_in[7];
    const float* b_hh2 = (const float*)d_in[8];
    const float* fc1_w = (const float*)d_in[9];
    const float* fc1_b = (const float*)d_in[10];
    const float* fc2_w = (const float*)d_in[11];
    const float* fc2_b = (const float*)d_in[12];
    float* out = (float*)d_out;

    // 2 elements per thread: 131072 threads, 1024 CTAs of 128
    lstm_kernel<<<B_TOTAL / (2 * NTL), NTL>>>(obs, w_ih1, w_hh1, b_ih1, b_hh1,
                                              w_ih2, w_hh2, b_ih2, b_hh2);

    pad_kernel<<<(128 * KPAD + 1023) / 1024, 1024>>>(fc1_w);

    const size_t dyn = FCDYN_FLOATS * sizeof(float);   // 73728 B
    cudaFuncSetAttribute(fc_kernel, cudaFuncAttributeMaxDynamicSharedMemorySize, (int)dyn);
    fc_kernel<<<B_TOTAL / 128, 256, dyn>>>(fc1_b, fc2_w, fc2_b, out);
}